// round 1
// baseline (speedup 1.0000x reference)
#include <cuda_runtime.h>
#include <math.h>

#define BB 64
#define SS 256
#define HH 1024
#define VV 10000
#define H3 3072

// ---------------- scratch (device globals; no allocations) ----------------
__device__ float g_u2p[8 * HH];
__device__ float g_u2[HH];
__device__ float g_gip[4 * BB * H3];
__device__ float g_gi[BB * H3];
__device__ float g_gh[2 * H3];          // double-buffered by step parity
__device__ float g_rnn[BB * HH];
__device__ float g_pscore[BB * SS];
__device__ float g_attnw[BB * SS];
__device__ float g_ctxp[4 * BB * HH];
__device__ float g_ctx[BB * HH];
__device__ float g_ccp[8 * BB * HH];
__device__ float g_co[BB * HH];
__device__ unsigned g_bar;

__global__ void k_reset() { g_bar = 0u; }

// ---------------- u2[k] = sum_h v[h] * W_attn[h][1024+k]  (partials) -------
__global__ void k_u2(const float* __restrict__ W_attn, const float* __restrict__ v_attn) {
    int hc = blockIdx.x >> 2;                       // 8 h-chunks of 128
    int k  = (blockIdx.x & 3) * 256 + threadIdx.x;  // 0..1023
    const float* wp = W_attn + 1024 + k;
    float a0 = 0.f, a1 = 0.f, a2 = 0.f, a3 = 0.f;
    int h0 = hc * 128;
    for (int h = h0; h < h0 + 128; h += 4) {
        a0 += v_attn[h + 0] * wp[(size_t)(h + 0) * 2048];
        a1 += v_attn[h + 1] * wp[(size_t)(h + 1) * 2048];
        a2 += v_attn[h + 2] * wp[(size_t)(h + 2) * 2048];
        a3 += v_attn[h + 3] * wp[(size_t)(h + 3) * 2048];
    }
    g_u2p[hc * HH + k] = (a0 + a1) + (a2 + a3);
}

__global__ void k_u2sum() {
    int k = blockIdx.x * 256 + threadIdx.x;
    float s = 0.f;
#pragma unroll
    for (int i = 0; i < 8; i++) s += g_u2p[i * HH + k];
    g_u2[k] = s;
}

// ---------------- gi partial GEMM: gi[t][r] partial over K-chunk ----------
// grid 192 = 48 row-tiles(64) x 4 k-splits(256). 256 threads, 4x4 micro-tile.
__global__ void k_gip(const int* __restrict__ seq, const float* __restrict__ emb,
                      const float* __restrict__ W_ih) {
    __shared__ float Wt[64 * 65];
    __shared__ float Et[64 * 65];
    __shared__ int   seq_s[64];
    int tid = threadIdx.x;
    int rt = blockIdx.x >> 2, ks = blockIdx.x & 3;
    int rb = rt * 64;
    if (tid < 64) seq_s[tid] = seq[tid];
    int rgq = tid & 15, bgq = tid >> 4;
    float acc[4][4] = {};
    for (int k0 = ks * 256; k0 < ks * 256 + 256; k0 += 64) {
        __syncthreads();
#pragma unroll
        for (int q = 0; q < 16; q++) {
            int idx = tid + 256 * q;
            int rl = idx >> 6, kl = idx & 63;
            Wt[rl * 65 + kl] = W_ih[(size_t)(rb + rl) * HH + k0 + kl];
            Et[rl * 65 + kl] = emb[(size_t)seq_s[rl] * HH + k0 + kl];
        }
        __syncthreads();
#pragma unroll
        for (int kk = 0; kk < 64; kk++) {
            float wv[4], xv[4];
#pragma unroll
            for (int i = 0; i < 4; i++) wv[i] = Wt[(rgq * 4 + i) * 65 + kk];
#pragma unroll
            for (int j = 0; j < 4; j++) xv[j] = Et[(bgq * 4 + j) * 65 + kk];
#pragma unroll
            for (int i = 0; i < 4; i++)
#pragma unroll
                for (int j = 0; j < 4; j++) acc[i][j] += wv[i] * xv[j];
        }
    }
#pragma unroll
    for (int i = 0; i < 4; i++)
#pragma unroll
        for (int j = 0; j < 4; j++) {
            int r = rb + rgq * 4 + i, t = bgq * 4 + j;
            g_gip[((size_t)ks * BB + t) * H3 + r] = acc[i][j];
        }
}

__global__ void k_gisum(const float* __restrict__ b_ih) {
    int idx = blockIdx.x * 256 + threadIdx.x;   // idx = t*3072 + r
    int r = idx % H3;
    float s = b_ih[r];
#pragma unroll
    for (int k = 0; k < 4; k++) s += g_gip[(size_t)k * BB * H3 + idx];
    g_gi[idx] = s;
}

// ---------------- persistent GRU: 128 blocks x 1024 thr, W_hh in registers --
__global__ void __launch_bounds__(1024, 1)
k_gru(const float* __restrict__ lh, const float* __restrict__ W_hh,
      const float* __restrict__ b_hh) {
    __shared__ float h_sh[HH];
    __shared__ float part[24][4];
    int tid = threadIdx.x;
    int rg = tid >> 7, cg = tid & 127;       // 8 row-groups x 3 rows, 128 col-groups
    int rowbase = blockIdx.x * 24;
    float w[3][8];
#pragma unroll
    for (int i = 0; i < 3; i++) {
        const float* wr = W_hh + (size_t)(rowbase + rg * 3 + i) * HH + cg;
#pragma unroll
        for (int j = 0; j < 8; j++) w[i][j] = wr[128 * j];
    }
    h_sh[tid] = lh[tid];
    float my_bhh = (tid < 24) ? b_hh[rowbase + tid] : 0.f;
    __syncthreads();
    int lane = tid & 31;
    int wig = (tid >> 5) & 3;                // warp within row-group
    for (int t = 0; t < BB; ++t) {
        float hv[8];
#pragma unroll
        for (int j = 0; j < 8; j++) hv[j] = h_sh[cg + 128 * j];
        float a0 = 0.f, a1 = 0.f, a2 = 0.f;
#pragma unroll
        for (int j = 0; j < 8; j++) {
            a0 += w[0][j] * hv[j];
            a1 += w[1][j] * hv[j];
            a2 += w[2][j] * hv[j];
        }
#pragma unroll
        for (int o = 16; o > 0; o >>= 1) {
            a0 += __shfl_xor_sync(0xffffffffu, a0, o);
            a1 += __shfl_xor_sync(0xffffffffu, a1, o);
            a2 += __shfl_xor_sync(0xffffffffu, a2, o);
        }
        if (lane == 0) {
            part[rg * 3 + 0][wig] = a0;
            part[rg * 3 + 1][wig] = a1;
            part[rg * 3 + 2][wig] = a2;
        }
        __syncthreads();
        if (tid < 24) {
            float gh = (part[tid][0] + part[tid][1]) + (part[tid][2] + part[tid][3]) + my_bhh;
            __stcg(&g_gh[(t & 1) * H3 + rowbase + tid], gh);
        }
        __syncthreads();
        if (tid == 0) {
            __threadfence();
            atomicAdd(&g_bar, 1u);
            unsigned tgt = (unsigned)(t + 1) * 128u;
            while (atomicAdd(&g_bar, 0u) < tgt) {}
        }
        __syncthreads();
        const float* gi = g_gi + (size_t)t * H3;
        float gi0 = gi[tid], gi1 = gi[HH + tid], gi2 = gi[2 * HH + tid];
        const float* ghp = g_gh + (t & 1) * H3;
        float gh0 = __ldcg(&ghp[tid]);
        float gh1 = __ldcg(&ghp[HH + tid]);
        float gh2 = __ldcg(&ghp[2 * HH + tid]);
        float r = 1.f / (1.f + expf(-(gi0 + gh0)));
        float z = 1.f / (1.f + expf(-(gi1 + gh1)));
        float n = tanhf(fmaf(r, gh2, gi2));
        float hold = h_sh[tid];
        float hnew = (1.f - z) * n + z * hold;
        __syncthreads();
        h_sh[tid] = hnew;
        if (blockIdx.x == 0) g_rnn[(size_t)t * HH + tid] = hnew;
        __syncthreads();
    }
}

// ---------------- pscore[b][s] = u2 . enc[s,b,:]  (warp per row) ----------
__global__ void k_pscore(const float* __restrict__ enc) {
    int wid = threadIdx.x >> 5, lane = threadIdx.x & 31;
    int rid = blockIdx.x * 8 + wid;          // rid = s*64 + b
    int s = rid >> 6, b = rid & 63;
    const float4* rp = (const float4*)(enc + (size_t)rid * HH);
    const float4* up = (const float4*)g_u2;
    float acc = 0.f;
#pragma unroll
    for (int j = 0; j < 8; j++) {
        float4 e = rp[lane + 32 * j];
        float4 u = up[lane + 32 * j];
        acc += e.x * u.x + e.y * u.y + e.z * u.z + e.w * u.w;
    }
#pragma unroll
    for (int o = 16; o > 0; o >>= 1) acc += __shfl_xor_sync(0xffffffffu, acc, o);
    if (lane == 0) g_pscore[b * SS + s] = acc;
}

// ---------------- softmax over S per b --------------------------------
__global__ void k_softmax(float* __restrict__ out_attn) {
    __shared__ float red[8];
    int b = blockIdx.x, tid = threadIdx.x, lane = tid & 31, wid = tid >> 5;
    float x = g_pscore[b * SS + tid];
    float m = x;
#pragma unroll
    for (int o = 16; o > 0; o >>= 1) m = fmaxf(m, __shfl_xor_sync(0xffffffffu, m, o));
    if (lane == 0) red[wid] = m;
    __syncthreads();
    m = red[0];
#pragma unroll
    for (int i = 1; i < 8; i++) m = fmaxf(m, red[i]);
    float e = expf(x - m);
    float s = e;
#pragma unroll
    for (int o = 16; o > 0; o >>= 1) s += __shfl_xor_sync(0xffffffffu, s, o);
    __syncthreads();
    if (lane == 0) red[wid] = s;
    __syncthreads();
    s = 0.f;
#pragma unroll
    for (int i = 0; i < 8; i++) s += red[i];
    float wgt = e / s;
    g_attnw[b * SS + tid] = wgt;
    out_attn[b * SS + tid] = wgt;
}

// ---------------- context partials: ctx[b][h] over 64-s chunks -----------
__global__ void k_ctxp(const float* __restrict__ enc) {
    __shared__ float ws[64];
    int tid = threadIdx.x;
    int b = blockIdx.x >> 4, sc = (blockIdx.x >> 2) & 3, hc = blockIdx.x & 3;
    if (tid < 64) ws[tid] = g_attnw[b * SS + sc * 64 + tid];
    __syncthreads();
    int h = hc * 256 + tid;
    const float* ep = enc + ((size_t)(sc * 64) * 64 + b) * HH + h;
    float a0 = 0.f, a1 = 0.f, a2 = 0.f, a3 = 0.f;
    for (int i = 0; i < 64; i += 4) {
        a0 += ws[i + 0] * ep[(size_t)(i + 0) * 64 * HH];
        a1 += ws[i + 1] * ep[(size_t)(i + 1) * 64 * HH];
        a2 += ws[i + 2] * ep[(size_t)(i + 2) * 64 * HH];
        a3 += ws[i + 3] * ep[(size_t)(i + 3) * 64 * HH];
    }
    g_ctxp[((size_t)sc * BB + b) * HH + h] = (a0 + a1) + (a2 + a3);
}

__global__ void k_ctxsum() {
    int idx = blockIdx.x * 256 + threadIdx.x;   // b*1024 + h
    float s = 0.f;
#pragma unroll
    for (int k = 0; k < 4; k++) s += g_ctxp[(size_t)k * BB * HH + idx];
    g_ctx[idx] = s;
}

// ---------------- concat GEMM partials: co[b][r], K=2048 ------------------
// grid 128 = 16 r-tiles(64) x 8 k-splits(256)
__global__ void k_ccp(const float* __restrict__ W_concat) {
    __shared__ float Wt[64 * 65];
    __shared__ float Xt[64 * 65];
    int tid = threadIdx.x;
    int rt = blockIdx.x >> 3, ks = blockIdx.x & 7;
    int rb = rt * 64;
    int rgq = tid & 15, bgq = tid >> 4;
    float acc[4][4] = {};
    for (int k0 = ks * 256; k0 < ks * 256 + 256; k0 += 64) {
        __syncthreads();
#pragma unroll
        for (int q = 0; q < 16; q++) {
            int idx = tid + 256 * q;
            int rl = idx >> 6, kl = idx & 63;
            Wt[rl * 65 + kl] = W_concat[(size_t)(rb + rl) * 2048 + k0 + kl];
            int k = k0 + kl;
            Xt[rl * 65 + kl] = (k < 1024) ? g_rnn[(size_t)rl * HH + k]
                                          : g_ctx[(size_t)rl * HH + (k - 1024)];
        }
        __syncthreads();
#pragma unroll
        for (int kk = 0; kk < 64; kk++) {
            float wv[4], xv[4];
#pragma unroll
            for (int i = 0; i < 4; i++) wv[i] = Wt[(rgq * 4 + i) * 65 + kk];
#pragma unroll
            for (int j = 0; j < 4; j++) xv[j] = Xt[(bgq * 4 + j) * 65 + kk];
#pragma unroll
            for (int i = 0; i < 4; i++)
#pragma unroll
                for (int j = 0; j < 4; j++) acc[i][j] += wv[i] * xv[j];
        }
    }
#pragma unroll
    for (int i = 0; i < 4; i++)
#pragma unroll
        for (int j = 0; j < 4; j++) {
            int r = rb + rgq * 4 + i, t = bgq * 4 + j;
            g_ccp[((size_t)ks * BB + t) * HH + r] = acc[i][j];
        }
}

__global__ void k_ccsum(const float* __restrict__ b_concat) {
    int idx = blockIdx.x * 256 + threadIdx.x;   // b*1024 + r
    int r = idx & 1023;
    float s = b_concat[r];
#pragma unroll
    for (int k = 0; k < 8; k++) s += g_ccp[(size_t)k * BB * HH + idx];
    g_co[idx] = tanhf(s);
}

// ---------------- output GEMM: out[b][v] = co[b] . W_out[v] + b_out[v] ----
__global__ void k_out(const float* __restrict__ W_out, const float* __restrict__ b_out,
                      float* __restrict__ out) {
    __shared__ float Wt[64 * 65];
    __shared__ float Ct[64 * 65];
    int tid = threadIdx.x;
    int vb = blockIdx.x * 64;
    int rgq = tid & 15, bgq = tid >> 4;
    float acc[4][4] = {};
    for (int k0 = 0; k0 < 1024; k0 += 64) {
        __syncthreads();
#pragma unroll
        for (int q = 0; q < 16; q++) {
            int idx = tid + 256 * q;
            int rl = idx >> 6, kl = idx & 63;
            int v = vb + rl;
            Wt[rl * 65 + kl] = (v < VV) ? W_out[(size_t)v * HH + k0 + kl] : 0.f;
            Ct[rl * 65 + kl] = g_co[(size_t)rl * HH + k0 + kl];
        }
        __syncthreads();
#pragma unroll
        for (int kk = 0; kk < 64; kk++) {
            float wv[4], cv[4];
#pragma unroll
            for (int i = 0; i < 4; i++) wv[i] = Wt[(rgq * 4 + i) * 65 + kk];
#pragma unroll
            for (int j = 0; j < 4; j++) cv[j] = Ct[(bgq * 4 + j) * 65 + kk];
#pragma unroll
            for (int i = 0; i < 4; i++)
#pragma unroll
                for (int j = 0; j < 4; j++) acc[i][j] += wv[i] * cv[j];
        }
    }
#pragma unroll
    for (int i = 0; i < 4; i++)
#pragma unroll
        for (int j = 0; j < 4; j++) {
            int v = vb + rgq * 4 + i, b = bgq * 4 + j;
            if (v < VV) out[(size_t)b * VV + v] = acc[i][j] + b_out[v];
        }
}

__global__ void k_hidden(float* __restrict__ out_hidden) {
    out_hidden[threadIdx.x] = g_rnn[63 * HH + threadIdx.x];
}

// ---------------- launch --------------------------------------------------
extern "C" void kernel_launch(void* const* d_in, const int* in_sizes, int n_in,
                              void* d_out, int out_size) {
    const int*   seq       = (const int*)  d_in[0];
    const float* last_h    = (const float*)d_in[1];
    const float* enc       = (const float*)d_in[2];
    const float* emb       = (const float*)d_in[3];
    const float* W_ih      = (const float*)d_in[4];
    const float* W_hh      = (const float*)d_in[5];
    const float* b_ih      = (const float*)d_in[6];
    const float* b_hh      = (const float*)d_in[7];
    const float* W_attn    = (const float*)d_in[8];
    // d_in[9] = b_attn  (cancels in softmax; unused)
    const float* v_attn    = (const float*)d_in[10];
    const float* W_concat  = (const float*)d_in[11];
    const float* b_concat  = (const float*)d_in[12];
    const float* W_out     = (const float*)d_in[13];
    const float* b_out     = (const float*)d_in[14];

    float* out      = (float*)d_out;               // [64,10000]
    float* out_hid  = out + (size_t)BB * VV;       // [1024]
    float* out_attn = out_hid + HH;                // [64,256]

    k_reset<<<1, 1>>>();
    k_u2<<<32, 256>>>(W_attn, v_attn);
    k_u2sum<<<4, 256>>>();
    k_gip<<<192, 256>>>(seq, emb, W_ih);
    k_gisum<<<768, 256>>>(b_ih);
    k_pscore<<<2048, 256>>>(enc);
    k_softmax<<<64, 256>>>(out_attn);
    k_ctxp<<<1024, 256>>>(enc);
    k_ctxsum<<<256, 256>>>();
    k_gru<<<128, 1024>>>(last_h, W_hh, b_hh);
    k_ccp<<<128, 256>>>(W_concat);
    k_ccsum<<<256, 256>>>(b_concat);
    k_out<<<157, 256>>>(W_out, b_out, out);
    k_hidden<<<1, 1024>>>(out_hid);
}

// round 2
// speedup vs baseline: 1.0318x; 1.0318x over previous
#include <cuda_runtime.h>
#include <math.h>

#define BB 64
#define SS 256
#define HH 1024
#define VV 10000
#define H3 3072
#define VPAD 10112   // 79 * 128

// ---------------- scratch (device globals; no allocations) ----------------
__device__ float g_u2p[32 * HH];
__device__ float g_u2[HH];
__device__ float g_gip[8 * BB * H3];      // [split][b][r]
__device__ float g_gi[BB * H3];           // [t][r]
__device__ float g_h[2 * HH];             // double-buffered h
__device__ float g_rnn[BB * HH];
__device__ float g_pscore[BB * SS];
__device__ float g_attnw[BB * SS];
__device__ float g_ctxp[4 * BB * HH];
__device__ float g_ctx[BB * HH];
__device__ float g_ccp[16 * BB * HH];     // [split][b][r]
__device__ float g_co[BB * HH];
__device__ float g_outp[2 * BB * VPAD];   // [split][b][v]
__device__ unsigned g_bar;

__global__ void k_reset() { g_bar = 0u; }

// ---------------- u2[k] = sum_h v[h] * W_attn[h][1024+k] ------------------
__global__ void k_u2(const float* __restrict__ W_attn, const float* __restrict__ v_attn) {
    int k  = blockIdx.x * 256 + threadIdx.x;   // 0..1023
    int h0 = blockIdx.y * 32;
    const float* wp = W_attn + 1024 + k;
    float a = 0.f;
#pragma unroll 8
    for (int h = h0; h < h0 + 32; h++)
        a += v_attn[h] * wp[(size_t)h * 2048];
    g_u2p[blockIdx.y * HH + k] = a;
}

__global__ void k_u2sum() {
    int k = blockIdx.x * 256 + threadIdx.x;
    float s = 0.f;
#pragma unroll
    for (int i = 0; i < 32; i++) s += g_u2p[i * HH + k];
    g_u2[k] = s;
}

// ============ common GEMM shape: 128 threads, tile 128r x 64b, micro 8x8 ===
// thread x = tid&15 owns rows {x + 16*i}, y = tid>>4 owns batches {y + 8*j}
// smem pad 33 -> conflict-free fragment loads.

// ---------------- gi partials: W_ih[3072,1024] x emb[b][1024] -------------
__global__ void __launch_bounds__(128) k_gip(const int* __restrict__ seq,
                                             const float* __restrict__ emb,
                                             const float* __restrict__ W_ih) {
    __shared__ float At[128 * 33];
    __shared__ float Bt[64 * 33];
    __shared__ int seq_s[64];
    int tid = threadIdx.x;
    int x = tid & 15, y = tid >> 4;
    int rb = blockIdx.x * 128;
    int kb = blockIdx.y * 128;            // 8 splits of 128
    if (tid < 64) seq_s[tid] = seq[tid];
    float acc[8][8] = {};
    for (int c = 0; c < 4; c++) {
        int k0 = kb + c * 32;
        __syncthreads();
#pragma unroll
        for (int q = 0; q < 32; q++) {
            int idx = tid + 128 * q;
            int r = idx >> 5, col = idx & 31;
            At[r * 33 + col] = W_ih[(size_t)(rb + r) * HH + k0 + col];
        }
#pragma unroll
        for (int q = 0; q < 16; q++) {
            int idx = tid + 128 * q;
            int b = idx >> 5, col = idx & 31;
            Bt[b * 33 + col] = emb[(size_t)seq_s[b] * HH + k0 + col];
        }
        __syncthreads();
#pragma unroll
        for (int kk = 0; kk < 32; kk++) {
            float a[8], bv[8];
#pragma unroll
            for (int i = 0; i < 8; i++) a[i] = At[(x + 16 * i) * 33 + kk];
#pragma unroll
            for (int j = 0; j < 8; j++) bv[j] = Bt[(y + 8 * j) * 33 + kk];
#pragma unroll
            for (int i = 0; i < 8; i++)
#pragma unroll
                for (int j = 0; j < 8; j++) acc[i][j] += a[i] * bv[j];
        }
    }
    float* P = g_gip + (size_t)blockIdx.y * BB * H3;
#pragma unroll
    for (int j = 0; j < 8; j++) {
        int b = y + 8 * j;
#pragma unroll
        for (int i = 0; i < 8; i++)
            P[(size_t)b * H3 + rb + x + 16 * i] = acc[i][j];
    }
}

__global__ void k_gisum(const float* __restrict__ b_ih) {
    int idx = blockIdx.x * 256 + threadIdx.x;   // t*3072 + r
    int r = idx % H3;
    float s = b_ih[r];
#pragma unroll
    for (int k = 0; k < 8; k++) s += g_gip[(size_t)k * BB * H3 + idx];
    g_gi[idx] = s;
}

// ---------------- persistent GRU: blocks own their h-slice ----------------
// 128 blocks x 1024 thr. Block owns j in [bid*8, bid*8+8): W_hh rows
// {j, 1024+j, 2048+j} -> gh never leaves the block. Only h (4KB) exchanged.
__global__ void __launch_bounds__(1024, 1)
k_gru(const float* __restrict__ lh, const float* __restrict__ W_hh,
      const float* __restrict__ b_hh) {
    __shared__ float h_sh[HH];
    __shared__ float part[8][3][4];
    int tid = threadIdx.x;
    int rg = tid >> 7, cg = tid & 127;   // rg: which of 8 owned j's
    int jj = blockIdx.x * 8 + rg;
    float w[3][8];
#pragma unroll
    for (int m = 0; m < 3; m++) {
        const float* wr = W_hh + (size_t)(m * HH + jj) * HH + cg;
#pragma unroll
        for (int i = 0; i < 8; i++) w[m][i] = wr[128 * i];
    }
    float bh0 = 0.f, bh1 = 0.f, bh2 = 0.f;
    int jmine = blockIdx.x * 8 + tid;    // valid for tid<8
    if (tid < 8) {
        bh0 = b_hh[jmine];
        bh1 = b_hh[HH + jmine];
        bh2 = b_hh[2 * HH + jmine];
    }
    h_sh[tid] = lh[tid];
    __syncthreads();
    int lane = tid & 31;
    int wig = (tid >> 5) & 3;
    for (int t = 0; t < BB; ++t) {
        // prefetch gi for this step (independent of h)
        float gi0 = 0.f, gi1 = 0.f, gi2 = 0.f;
        if (tid < 8) {
            const float* gp = g_gi + (size_t)t * H3;
            gi0 = __ldg(&gp[jmine]);
            gi1 = __ldg(&gp[HH + jmine]);
            gi2 = __ldg(&gp[2 * HH + jmine]);
        }
        float hv[8];
#pragma unroll
        for (int i = 0; i < 8; i++) hv[i] = h_sh[cg + 128 * i];
        float a0 = 0.f, a1 = 0.f, a2 = 0.f;
#pragma unroll
        for (int i = 0; i < 8; i++) {
            a0 += w[0][i] * hv[i];
            a1 += w[1][i] * hv[i];
            a2 += w[2][i] * hv[i];
        }
#pragma unroll
        for (int o = 16; o > 0; o >>= 1) {
            a0 += __shfl_xor_sync(0xffffffffu, a0, o);
            a1 += __shfl_xor_sync(0xffffffffu, a1, o);
            a2 += __shfl_xor_sync(0xffffffffu, a2, o);
        }
        if (lane == 0) {
            part[rg][0][wig] = a0;
            part[rg][1][wig] = a1;
            part[rg][2][wig] = a2;
        }
        __syncthreads();
        if (tid < 8) {
            float g0 = (part[tid][0][0] + part[tid][0][1]) + (part[tid][0][2] + part[tid][0][3]) + bh0;
            float g1 = (part[tid][1][0] + part[tid][1][1]) + (part[tid][1][2] + part[tid][1][3]) + bh1;
            float g2 = (part[tid][2][0] + part[tid][2][1]) + (part[tid][2][2] + part[tid][2][3]) + bh2;
            float r = 1.f / (1.f + __expf(-(gi0 + g0)));
            float z = 1.f / (1.f + __expf(-(gi1 + g1)));
            float n = tanhf(fmaf(r, g2, gi2));
            float hnew = (1.f - z) * n + z * h_sh[jmine];
            g_rnn[(size_t)t * HH + jmine] = hnew;
            __stcg(&g_h[((t + 1) & 1) * HH + jmine], hnew);
            __threadfence();
        }
        __syncthreads();
        if (tid == 0) {
            atomicAdd(&g_bar, 1u);
            unsigned tgt = (unsigned)(t + 1) * 128u;
            while (atomicAdd(&g_bar, 0u) < tgt) {}
            __threadfence();
        }
        __syncthreads();
        float hload = __ldcg(&g_h[((t + 1) & 1) * HH + tid]);
        __syncthreads();
        h_sh[tid] = hload;
        __syncthreads();
    }
}

// ---------------- pscore[b][s] = u2 . enc[s,b,:] --------------------------
__global__ void k_pscore(const float* __restrict__ enc) {
    int wid = threadIdx.x >> 5, lane = threadIdx.x & 31;
    int rid = blockIdx.x * 8 + wid;          // rid = s*64 + b
    int s = rid >> 6, b = rid & 63;
    const float4* rp = (const float4*)(enc + (size_t)rid * HH);
    const float4* up = (const float4*)g_u2;
    float acc = 0.f;
#pragma unroll
    for (int j = 0; j < 8; j++) {
        float4 e = rp[lane + 32 * j];
        float4 u = up[lane + 32 * j];
        acc += e.x * u.x + e.y * u.y + e.z * u.z + e.w * u.w;
    }
#pragma unroll
    for (int o = 16; o > 0; o >>= 1) acc += __shfl_xor_sync(0xffffffffu, acc, o);
    if (lane == 0) g_pscore[b * SS + s] = acc;
}

// ---------------- softmax over S per b ------------------------------------
__global__ void k_softmax(float* __restrict__ out_attn) {
    __shared__ float red[8];
    int b = blockIdx.x, tid = threadIdx.x, lane = tid & 31, wid = tid >> 5;
    float x = g_pscore[b * SS + tid];
    float m = x;
#pragma unroll
    for (int o = 16; o > 0; o >>= 1) m = fmaxf(m, __shfl_xor_sync(0xffffffffu, m, o));
    if (lane == 0) red[wid] = m;
    __syncthreads();
    m = red[0];
#pragma unroll
    for (int i = 1; i < 8; i++) m = fmaxf(m, red[i]);
    float e = __expf(x - m);
    float s = e;
#pragma unroll
    for (int o = 16; o > 0; o >>= 1) s += __shfl_xor_sync(0xffffffffu, s, o);
    __syncthreads();
    if (lane == 0) red[wid] = s;
    __syncthreads();
    s = 0.f;
#pragma unroll
    for (int i = 0; i < 8; i++) s += red[i];
    float wgt = e / s;
    g_attnw[b * SS + tid] = wgt;
    out_attn[b * SS + tid] = wgt;
}

// ---------------- context partials ----------------------------------------
__global__ void k_ctxp(const float* __restrict__ enc) {
    __shared__ float ws[64];
    int tid = threadIdx.x;
    int b = blockIdx.x >> 4, sc = (blockIdx.x >> 2) & 3, hc = blockIdx.x & 3;
    if (tid < 64) ws[tid] = g_attnw[b * SS + sc * 64 + tid];
    __syncthreads();
    int h = hc * 256 + tid;
    const float* ep = enc + ((size_t)(sc * 64) * 64 + b) * HH + h;
    float a0 = 0.f, a1 = 0.f, a2 = 0.f, a3 = 0.f;
    for (int i = 0; i < 64; i += 4) {
        a0 += ws[i + 0] * ep[(size_t)(i + 0) * 64 * HH];
        a1 += ws[i + 1] * ep[(size_t)(i + 1) * 64 * HH];
        a2 += ws[i + 2] * ep[(size_t)(i + 2) * 64 * HH];
        a3 += ws[i + 3] * ep[(size_t)(i + 3) * 64 * HH];
    }
    g_ctxp[((size_t)sc * BB + b) * HH + h] = (a0 + a1) + (a2 + a3);
}

__global__ void k_ctxsum() {
    int idx = blockIdx.x * 256 + threadIdx.x;   // b*1024 + h
    float s = 0.f;
#pragma unroll
    for (int k = 0; k < 4; k++) s += g_ctxp[(size_t)k * BB * HH + idx];
    g_ctx[idx] = s;
}

// ---------------- concat GEMM: W_concat[1024,2048] x [rnn|ctx] ------------
__global__ void __launch_bounds__(128) k_ccp(const float* __restrict__ W_concat) {
    __shared__ float At[128 * 33];
    __shared__ float Bt[64 * 33];
    int tid = threadIdx.x;
    int x = tid & 15, y = tid >> 4;
    int rb = blockIdx.x * 128;
    int kb = blockIdx.y * 128;            // 16 splits of 128 over K=2048
    const float* Bsrc = (kb < 1024) ? g_rnn : g_ctx;
    int kboff = (kb < 1024) ? kb : (kb - 1024);
    float acc[8][8] = {};
    for (int c = 0; c < 4; c++) {
        int k0 = kb + c * 32;
        int kb0 = kboff + c * 32;
        __syncthreads();
#pragma unroll
        for (int q = 0; q < 32; q++) {
            int idx = tid + 128 * q;
            int r = idx >> 5, col = idx & 31;
            At[r * 33 + col] = W_concat[(size_t)(rb + r) * 2048 + k0 + col];
        }
#pragma unroll
        for (int q = 0; q < 16; q++) {
            int idx = tid + 128 * q;
            int b = idx >> 5, col = idx & 31;
            Bt[b * 33 + col] = Bsrc[(size_t)b * HH + kb0 + col];
        }
        __syncthreads();
#pragma unroll
        for (int kk = 0; kk < 32; kk++) {
            float a[8], bv[8];
#pragma unroll
            for (int i = 0; i < 8; i++) a[i] = At[(x + 16 * i) * 33 + kk];
#pragma unroll
            for (int j = 0; j < 8; j++) bv[j] = Bt[(y + 8 * j) * 33 + kk];
#pragma unroll
            for (int i = 0; i < 8; i++)
#pragma unroll
                for (int j = 0; j < 8; j++) acc[i][j] += a[i] * bv[j];
        }
    }
    float* P = g_ccp + (size_t)blockIdx.y * BB * HH;
#pragma unroll
    for (int j = 0; j < 8; j++) {
        int b = y + 8 * j;
#pragma unroll
        for (int i = 0; i < 8; i++)
            P[(size_t)b * HH + rb + x + 16 * i] = acc[i][j];
    }
}

__global__ void k_ccsum(const float* __restrict__ b_concat) {
    int idx = blockIdx.x * 256 + threadIdx.x;   // b*1024 + r
    int r = idx & 1023;
    float s = b_concat[r];
#pragma unroll
    for (int k = 0; k < 16; k++) s += g_ccp[(size_t)k * BB * HH + idx];
    g_co[idx] = tanhf(s);
}

// ---------------- output GEMM: W_out[10000,1024] x co[64,1024] ------------
__global__ void __launch_bounds__(128) k_out(const float* __restrict__ W_out) {
    __shared__ float At[128 * 33];
    __shared__ float Bt[64 * 33];
    int tid = threadIdx.x;
    int x = tid & 15, y = tid >> 4;
    int rb = blockIdx.x * 128;
    int kb = blockIdx.y * 512;            // 2 splits of 512
    float acc[8][8] = {};
    for (int c = 0; c < 16; c++) {
        int k0 = kb + c * 32;
        __syncthreads();
#pragma unroll
        for (int q = 0; q < 32; q++) {
            int idx = tid + 128 * q;
            int r = idx >> 5, col = idx & 31;
            int gr = rb + r;
            At[r * 33 + col] = (gr < VV) ? W_out[(size_t)gr * HH + k0 + col] : 0.f;
        }
#pragma unroll
        for (int q = 0; q < 16; q++) {
            int idx = tid + 128 * q;
            int b = idx >> 5, col = idx & 31;
            Bt[b * 33 + col] = g_co[(size_t)b * HH + k0 + col];
        }
        __syncthreads();
#pragma unroll
        for (int kk = 0; kk < 32; kk++) {
            float a[8], bv[8];
#pragma unroll
            for (int i = 0; i < 8; i++) a[i] = At[(x + 16 * i) * 33 + kk];
#pragma unroll
            for (int j = 0; j < 8; j++) bv[j] = Bt[(y + 8 * j) * 33 + kk];
#pragma unroll
            for (int i = 0; i < 8; i++)
#pragma unroll
                for (int j = 0; j < 8; j++) acc[i][j] += a[i] * bv[j];
        }
    }
    float* P = g_outp + (size_t)blockIdx.y * BB * VPAD;
#pragma unroll
    for (int j = 0; j < 8; j++) {
        int b = y + 8 * j;
#pragma unroll
        for (int i = 0; i < 8; i++)
            P[(size_t)b * VPAD + rb + x + 16 * i] = acc[i][j];
    }
}

__global__ void k_outsum(const float* __restrict__ b_out, float* __restrict__ out) {
    int idx = blockIdx.x * 256 + threadIdx.x;
    if (idx >= BB * VV) return;
    int b = idx / VV, v = idx % VV;
    out[idx] = b_out[v] + g_outp[(size_t)b * VPAD + v]
                        + g_outp[(size_t)(BB + b) * VPAD + v];
}

__global__ void k_hidden(float* __restrict__ out_hidden) {
    out_hidden[threadIdx.x] = g_rnn[63 * HH + threadIdx.x];
}

// ---------------- launch --------------------------------------------------
extern "C" void kernel_launch(void* const* d_in, const int* in_sizes, int n_in,
                              void* d_out, int out_size) {
    const int*   seq       = (const int*)  d_in[0];
    const float* last_h    = (const float*)d_in[1];
    const float* enc       = (const float*)d_in[2];
    const float* emb       = (const float*)d_in[3];
    const float* W_ih      = (const float*)d_in[4];
    const float* W_hh      = (const float*)d_in[5];
    const float* b_ih      = (const float*)d_in[6];
    const float* b_hh      = (const float*)d_in[7];
    const float* W_attn    = (const float*)d_in[8];
    // d_in[9] = b_attn  (cancels in softmax; unused)
    const float* v_attn    = (const float*)d_in[10];
    const float* W_concat  = (const float*)d_in[11];
    const float* b_concat  = (const float*)d_in[12];
    const float* W_out     = (const float*)d_in[13];
    const float* b_out     = (const float*)d_in[14];

    float* out      = (float*)d_out;               // [64,10000]
    float* out_hid  = out + (size_t)BB * VV;       // [1024]
    float* out_attn = out_hid + HH;                // [64,256]

    k_reset<<<1, 1>>>();
    k_gip<<<dim3(24, 8), 128>>>(seq, emb, W_ih);
    k_gisum<<<768, 256>>>(b_ih);
    k_gru<<<128, 1024>>>(last_h, W_hh, b_hh);
    k_u2<<<dim3(4, 32), 256>>>(W_attn, v_attn);
    k_u2sum<<<4, 256>>>();
    k_pscore<<<2048, 256>>>(enc);
    k_softmax<<<64, 256>>>(out_attn);
    k_ctxp<<<1024, 256>>>(enc);
    k_ctxsum<<<256, 256>>>();
    k_ccp<<<dim3(8, 16), 128>>>(W_concat);
    k_ccsum<<<256, 256>>>(b_concat);
    k_out<<<dim3(79, 2), 128>>>(W_out);
    k_outsum<<<2500, 256>>>(b_out, out);
    k_hidden<<<1, 1024>>>(out_hid);
}